// round 8
// baseline (speedup 1.0000x reference)
#include <cuda_runtime.h>
#include <math.h>
#include <stdint.h>

// MonotonicSpline: y[i] = cubic uniform B-spline(clip(x[i],0,1)).
// coef[0]=c0; coef[j]=c0 + sum_{i<j}(MIN+(MAX-MIN)*sigmoid(raw_delta[i])).
// Uniform knots h=1/40 -> per-segment cubic y = ((a*u+b)*u+c)*u+d, u=frac(40x).
// Fused kernel, exact-residency grid (148 SMs x 8 blocks). x is streamed
// through a per-thread 4-deep cp.async smem ring: pipeline depth WITHOUT
// register cost (register pipelines regressed occupancy in R3/R7). No
// barriers in the loop: each thread consumes only its own ring slot.
// 8-way bank-replicated smem poly table (conflict-free LDS.128).

static constexpr int   NUM_KNOTS  = 40;
static constexpr float MIN_DELTA  = 0.5f / NUM_KNOTS;
static constexpr float MAX_DELTA  = 3.0f / NUM_KNOTS;
static constexpr int   THREADS    = 256;
static constexpr int   STAGES     = 4;          // cp.async ring depth
static constexpr int   BLOCKS_SM  = 8;
static constexpr int   MAX_BLOCKS = 148 * BLOCKS_SM;

__device__ __forceinline__ void cp_async16(uint32_t smem_dst, const float4* gsrc) {
    asm volatile("cp.async.cg.shared.global [%0], [%1], 16;"
                 :: "r"(smem_dst), "l"(gsrc));
}
__device__ __forceinline__ void cp_commit() {
    asm volatile("cp.async.commit_group;");
}
__device__ __forceinline__ void cp_wait_3() {
    asm volatile("cp.async.wait_group 3;");   // STAGES-1
}

__device__ __forceinline__ float eval_one(float xv, const float4* __restrict__ rep,
                                          int lane8) {
    float t   = __saturatef(xv) * (float)NUM_KNOTS;   // t in [0,40]
    int   idx = min(__float2int_rz(t), NUM_KNOTS - 1);
    float u   = t - (float)idx;                        // u in [0,1]
    float4 p  = rep[idx * 8 + lane8];                  // conflict-free LDS.128
    return ((p.w * u + p.z) * u + p.y) * u + p.x;
}

__global__ void __launch_bounds__(THREADS, BLOCKS_SM)
spline_fused_kernel(const float* __restrict__ x,
                    const float* __restrict__ c0,
                    const float* __restrict__ raw_delta,
                    float* __restrict__ y,
                    int n4, int n) {
    __shared__ float  coef[NUM_KNOTS + 3];          // 43
    __shared__ float4 rep[NUM_KNOTS * 8];           // 5 KB replicated table
    __shared__ float4 stage[STAGES][THREADS];       // 16 KB cp.async ring

    const int tid    = threadIdx.x;
    const int lane   = tid & 31;
    const int stride = gridDim.x * THREADS;
    const float4* __restrict__ x4 = reinterpret_cast<const float4*>(x);
    float4* __restrict__ y4 = reinterpret_cast<float4*>(y);

    // ---- prime the async ring BEFORE the table prologue ----
    const int i0 = blockIdx.x * THREADS + tid;
    uint32_t slot[STAGES];
    #pragma unroll
    for (int s = 0; s < STAGES; ++s) {
        slot[s] = (uint32_t)__cvta_generic_to_shared(&stage[s][tid]);
        int idx = i0 + s * stride;
        if (idx < n4) cp_async16(slot[s], x4 + idx);
        cp_commit();                    // one group per stage (may be empty)
    }

    // ---- warp 0: sigmoid deltas -> scan -> coef -> replicated poly table ----
    if (tid < 32) {
        const float scale = MAX_DELTA - MIN_DELTA;
        float d0 = MIN_DELTA + scale / (1.0f + __expf(-raw_delta[lane]));
        float d1 = 0.0f;
        if (lane < 10)
            d1 = MIN_DELTA + scale / (1.0f + __expf(-raw_delta[lane + 32]));
        #pragma unroll
        for (int off = 1; off < 32; off <<= 1) {
            float t0 = __shfl_up_sync(0xffffffffu, d0, off);
            float t1 = __shfl_up_sync(0xffffffffu, d1, off);
            if (lane >= off) { d0 += t0; d1 += t1; }
        }
        float tot0 = __shfl_sync(0xffffffffu, d0, 31);
        float c0v  = __ldg(c0);
        if (lane == 0) coef[0] = c0v;
        coef[lane + 1] = c0v + d0;                        // coef[1..32]
        if (lane < 10) coef[lane + 33] = c0v + tot0 + d1; // coef[33..42]
        __syncwarp();
        #pragma unroll
        for (int e = lane; e < NUM_KNOTS * 8; e += 32) {  // conflict-free STS.128
            int j = e >> 3;
            float p0 = coef[j], p1 = coef[j + 1], p2 = coef[j + 2], p3 = coef[j + 3];
            float4 o;
            o.x = (p0 + 4.0f * p1 + p2) * (1.0f / 6.0f);
            o.y = (p2 - p0) * 0.5f;
            o.z = (p0 - 2.0f * p1 + p2) * 0.5f;
            o.w = (p3 - p0 + 3.0f * (p1 - p2)) * (1.0f / 6.0f);
            rep[e] = o;
        }
    }
    __syncthreads();

    // ---- per-thread depth-4 async-pipelined loop (no barriers) ----
    const int lane8 = tid & 7;
    int i = i0, s = 0;
    #pragma unroll 1
    while (i < n4) {
        cp_wait_3();                          // oldest group (stage s) complete
        float4 v = stage[s][tid];             // own slot: conflict-free LDS.128

        int inext = i + STAGES * stride;      // refill this stage
        if (inext < n4) cp_async16(slot[s], x4 + inext);
        cp_commit();                          // keeps pending count at STAGES

        float4 o;
        o.x = eval_one(v.x, rep, lane8);
        o.y = eval_one(v.y, rep, lane8);
        o.z = eval_one(v.z, rep, lane8);
        o.w = eval_one(v.w, rep, lane8);
        y4[i] = o;

        i += stride;
        s = (s + 1) & (STAGES - 1);
    }

    // scalar tail (n % 4 != 0) — block 0 only
    if (blockIdx.x == 0) {
        int j = n4 * 4 + tid;
        if (j < n) y[j] = eval_one(x[j], rep, lane8);
    }
}

extern "C" void kernel_launch(void* const* d_in, const int* in_sizes, int n_in,
                              void* d_out, int out_size) {
    const float* x         = (const float*)d_in[0];
    // d_in[1] = grid (uniform; values implied by construction)
    const float* c0        = (const float*)d_in[2];
    const float* raw_delta = (const float*)d_in[3];
    float* y = (float*)d_out;

    int n  = in_sizes[0];
    int n4 = n / 4;

    int blocks = (n4 + THREADS - 1) / THREADS;
    if (blocks > MAX_BLOCKS) blocks = MAX_BLOCKS;
    if (blocks == 0) blocks = 1;

    spline_fused_kernel<<<blocks, THREADS>>>(x, c0, raw_delta, y, n4, n);
}

// round 9
// speedup vs baseline: 1.2038x; 1.2038x over previous
#include <cuda_runtime.h>
#include <math.h>

// MonotonicSpline: y[i] = cubic uniform B-spline(clip(x[i],0,1)).
// coef[0]=c0; coef[j]=c0 + sum_{i<j}(MIN+(MAX-MIN)*sigmoid(raw_delta[i])).
// Uniform knots h=1/40 -> per-segment cubic y = ((a*u+b)*u+c)*u+d, u=frac(40x).
// Round-2 structure (fastest eval measured: 9.0us) + fused prologue:
//  - ITEMS=4, contiguous per-block chunks, immediate-offset addressing
//  - 1024 blocks, __launch_bounds__(256,8) pins regs<=32 -> ONE resident wave
//  - 4 LDG.128 issued before the warp-0 table prologue (shadows its latency)
//  - 8-way bank-replicated smem poly table, conflict-free LDS.128
// Evidence-based removals: no grid-stride (ALU 2x), no reg pipeline (R7),
// no cp.async (R8), no ldcs/stcs.

static constexpr int   NUM_KNOTS = 40;
static constexpr float MIN_DELTA = 0.5f / NUM_KNOTS;
static constexpr float MAX_DELTA = 3.0f / NUM_KNOTS;
static constexpr int   THREADS   = 256;
static constexpr int   ITEMS     = 4;

__device__ __forceinline__ float eval_one(float xv, const float4* __restrict__ rep,
                                          int lane8) {
    float t   = __saturatef(xv) * (float)NUM_KNOTS;   // t in [0,40]
    int   idx = min(__float2int_rz(t), NUM_KNOTS - 1);
    float u   = t - (float)idx;                        // u in [0,1]
    float4 p  = rep[idx * 8 + lane8];                  // conflict-free LDS.128
    return ((p.w * u + p.z) * u + p.y) * u + p.x;
}

__global__ void __launch_bounds__(THREADS, 8)
spline_fused_kernel(const float* __restrict__ x,
                    const float* __restrict__ c0,
                    const float* __restrict__ raw_delta,
                    float* __restrict__ y,
                    int n4, int n) {
    __shared__ float  coef[NUM_KNOTS + 3];      // 43
    __shared__ float4 rep[NUM_KNOTS * 8];       // 8-way replicated table, 5 KB

    const int tid  = threadIdx.x;
    const int lane = tid & 31;
    const int base = blockIdx.x * (THREADS * ITEMS) + tid;
    const bool full = (blockIdx.x + 1) * (THREADS * ITEMS) <= n4;
    const float4* __restrict__ x4 = reinterpret_cast<const float4*>(x);
    float4* __restrict__ y4 = reinterpret_cast<float4*>(y);

    // ---- issue data loads FIRST (immediate offsets) to shadow the prologue ----
    float4 v0, v1, v2, v3;
    if (full) {
        v0 = x4[base + 0 * THREADS];
        v1 = x4[base + 1 * THREADS];
        v2 = x4[base + 2 * THREADS];
        v3 = x4[base + 3 * THREADS];
    } else {
        if (base + 0 * THREADS < n4) v0 = x4[base + 0 * THREADS];
        if (base + 1 * THREADS < n4) v1 = x4[base + 1 * THREADS];
        if (base + 2 * THREADS < n4) v2 = x4[base + 2 * THREADS];
        if (base + 3 * THREADS < n4) v3 = x4[base + 3 * THREADS];
    }

    // ---- warp 0: sigmoid deltas -> scan -> coef -> replicated poly table ----
    if (tid < 32) {
        const float scale = MAX_DELTA - MIN_DELTA;
        float d0 = MIN_DELTA + scale / (1.0f + __expf(-raw_delta[lane]));
        float d1 = 0.0f;
        if (lane < 10)
            d1 = MIN_DELTA + scale / (1.0f + __expf(-raw_delta[lane + 32]));
        #pragma unroll
        for (int off = 1; off < 32; off <<= 1) {
            float t0 = __shfl_up_sync(0xffffffffu, d0, off);
            float t1 = __shfl_up_sync(0xffffffffu, d1, off);
            if (lane >= off) { d0 += t0; d1 += t1; }
        }
        float tot0 = __shfl_sync(0xffffffffu, d0, 31);
        float c0v  = __ldg(c0);
        if (lane == 0) coef[0] = c0v;
        coef[lane + 1] = c0v + d0;                        // coef[1..32]
        if (lane < 10) coef[lane + 33] = c0v + tot0 + d1; // coef[33..42]
        __syncwarp();
        #pragma unroll
        for (int e = lane; e < NUM_KNOTS * 8; e += 32) {  // conflict-free STS.128
            int j = e >> 3;
            float p0 = coef[j], p1 = coef[j + 1], p2 = coef[j + 2], p3 = coef[j + 3];
            float4 o;
            o.x = (p0 + 4.0f * p1 + p2) * (1.0f / 6.0f);
            o.y = (p2 - p0) * 0.5f;
            o.z = (p0 - 2.0f * p1 + p2) * 0.5f;
            o.w = (p3 - p0 + 3.0f * (p1 - p2)) * (1.0f / 6.0f);
            rep[e] = o;
        }
    }
    __syncthreads();

    // ---- gather + Horner + store (immediate-offset STG.128) ----
    const int lane8 = tid & 7;
    if (full) {
        float4 o;
        o.x = eval_one(v0.x, rep, lane8); o.y = eval_one(v0.y, rep, lane8);
        o.z = eval_one(v0.z, rep, lane8); o.w = eval_one(v0.w, rep, lane8);
        y4[base + 0 * THREADS] = o;
        o.x = eval_one(v1.x, rep, lane8); o.y = eval_one(v1.y, rep, lane8);
        o.z = eval_one(v1.z, rep, lane8); o.w = eval_one(v1.w, rep, lane8);
        y4[base + 1 * THREADS] = o;
        o.x = eval_one(v2.x, rep, lane8); o.y = eval_one(v2.y, rep, lane8);
        o.z = eval_one(v2.z, rep, lane8); o.w = eval_one(v2.w, rep, lane8);
        y4[base + 2 * THREADS] = o;
        o.x = eval_one(v3.x, rep, lane8); o.y = eval_one(v3.y, rep, lane8);
        o.z = eval_one(v3.z, rep, lane8); o.w = eval_one(v3.w, rep, lane8);
        y4[base + 3 * THREADS] = o;
    } else {
        float4 vv[4] = {v0, v1, v2, v3};
        #pragma unroll
        for (int it = 0; it < ITEMS; ++it) {
            int i = base + it * THREADS;
            if (i < n4) {
                float4 o;
                o.x = eval_one(vv[it].x, rep, lane8);
                o.y = eval_one(vv[it].y, rep, lane8);
                o.z = eval_one(vv[it].z, rep, lane8);
                o.w = eval_one(vv[it].w, rep, lane8);
                y4[i] = o;
            }
        }
    }

    // scalar tail (n % 4 != 0) — block 0 only
    if (blockIdx.x == 0) {
        int j = n4 * 4 + tid;
        if (j < n) y[j] = eval_one(x[j], rep, lane8);
    }
}

extern "C" void kernel_launch(void* const* d_in, const int* in_sizes, int n_in,
                              void* d_out, int out_size) {
    const float* x         = (const float*)d_in[0];
    // d_in[1] = grid (uniform; values implied by construction)
    const float* c0        = (const float*)d_in[2];
    const float* raw_delta = (const float*)d_in[3];
    float* y = (float*)d_out;

    int n  = in_sizes[0];
    int n4 = n / 4;

    int per_block = THREADS * ITEMS;
    int blocks = (n4 + per_block - 1) / per_block;
    if (blocks == 0) blocks = 1;

    spline_fused_kernel<<<blocks, THREADS>>>(x, c0, raw_delta, y, n4, n);
}